// round 2
// baseline (speedup 1.0000x reference)
#include <cuda_runtime.h>
#include <math.h>

// Problem constants (fixed shapes)
#define BB 4
#define NN 1024
#define EE 16
#define SS 4
#define HH 64          // AH == PH == 64
#define NT 32          // tiles per dimension (N/32)
#define NTRI (NT*(NT+1)/2)   // 528 triangular tiles per batch

// ---------------- device scratch (no allocations allowed) ----------------
__device__ float g_cp[BB * NN * 2];        // centered positions
__device__ float g_Tatom[SS * HH];         // embed @ aW0[5:21]
__device__ float g_Tpi[SS * HH];           // embed @ pW0[5:21]
__device__ float g_Tpj[SS * HH];           // embed @ pW0[21:37]
__device__ float g_ACbase[BB * HH];        // Ex*aW0[2]+Ey*aW0[3]+en*aW0[4]+ab0
__device__ float g_Pbase[BB * HH];         // en*pW0[4]+pb0
__device__ float g_pairPart[BB * NTRI];    // per-block pair partial sums
__device__ float g_atomPart[BB * 4];       // per-block atom partial sums

__device__ __forceinline__ float silu_f(float x) {
    return x / (1.0f + __expf(-x));
}

// ---------------- prep: means, cp, tables ----------------
__global__ void prep_kernel(const float* __restrict__ pos,
                            const float* __restrict__ ef,
                            const float* __restrict__ embed,
                            const float* __restrict__ aW0,
                            const float* __restrict__ ab0,
                            const float* __restrict__ pW0,
                            const float* __restrict__ pb0) {
    const int tid = threadIdx.x; // 256 threads
    __shared__ float sx_[256], sy_[256];

    for (int b = 0; b < BB; b++) {
        float sx = 0.f, sy = 0.f;
        for (int n = tid; n < NN; n += 256) {
            sx += pos[(b * NN + n) * 2 + 0];
            sy += pos[(b * NN + n) * 2 + 1];
        }
        sx_[tid] = sx; sy_[tid] = sy;
        __syncthreads();
        for (int s = 128; s > 0; s >>= 1) {
            if (tid < s) { sx_[tid] += sx_[tid + s]; sy_[tid] += sy_[tid + s]; }
            __syncthreads();
        }
        const float mx = sx_[0] * (1.f / NN);
        const float my = sy_[0] * (1.f / NN);
        for (int n = tid; n < NN; n += 256) {
            g_cp[(b * NN + n) * 2 + 0] = pos[(b * NN + n) * 2 + 0] - mx;
            g_cp[(b * NN + n) * 2 + 1] = pos[(b * NN + n) * 2 + 1] - my;
        }
        __syncthreads();
    }

    // species tables: 256 entries total, one per thread
    {
        const int s = tid >> 6, k = tid & 63;
        float ta = 0.f, tpi = 0.f, tpj = 0.f;
#pragma unroll
        for (int e = 0; e < EE; e++) {
            const float em = embed[s * EE + e];
            ta  += em * aW0[(5 + e) * HH + k];
            tpi += em * pW0[(5 + e) * HH + k];
            tpj += em * pW0[(21 + e) * HH + k];
        }
        g_Tatom[tid] = ta; g_Tpi[tid] = tpi; g_Tpj[tid] = tpj;
    }
    // per-batch base rows: 256 entries (BB*HH)
    {
        const int b = tid >> 6, k = tid & 63;
        const float Ex = ef[b * 2], Ey = ef[b * 2 + 1];
        const float en = sqrtf(Ex * Ex + Ey * Ey);
        g_ACbase[tid] = Ex * aW0[2 * HH + k] + Ey * aW0[3 * HH + k]
                      + en * aW0[4 * HH + k] + ab0[k];
        g_Pbase[tid]  = en * pW0[4 * HH + k] + pb0[k];
    }
}

// ---------------- atom channel ----------------
__global__ __launch_bounds__(256, 2)
void atom_kernel(const int* __restrict__ species,
                 const float* __restrict__ aW0,
                 const float* __restrict__ aW1,
                 const float* __restrict__ ab1,
                 const float* __restrict__ aW2,
                 const float* __restrict__ ab2) {
    __shared__ float sW1T[HH * HH];       // transposed: [k][j]
    __shared__ float sTA[SS * 65];        // padded stride 65 (bank-conflict free)
    __shared__ float2 sGeo[HH];
    __shared__ float sB1[HH], sW2[HH];
    __shared__ float sRed[256];

    const int tid = threadIdx.x;
    const int b = blockIdx.y;
    const int n = blockIdx.x * 256 + tid;

    for (int idx = tid; idx < HH * HH; idx += 256) {
        const int j = idx >> 6, k = idx & 63;
        sW1T[k * HH + j] = aW1[idx];
    }
    for (int idx = tid; idx < SS * HH; idx += 256) {
        const int s = idx >> 6, k = idx & 63;
        sTA[s * 65 + k] = g_ACbase[b * HH + k] + g_Tatom[s * HH + k];
    }
    if (tid < HH) {
        sGeo[tid] = make_float2(aW0[tid], aW0[HH + tid]);
        sB1[tid] = ab1[tid];
        sW2[tid] = aW2[tid];
    }
    __syncthreads();

    const float cx = g_cp[(b * NN + n) * 2 + 0];
    const float cy = g_cp[(b * NN + n) * 2 + 1];
    const int sp = species[b * NN + n];
    const float* ta = &sTA[sp * 65];

    float h0[HH];
#pragma unroll
    for (int k = 0; k < HH; k++) {
        const float2 g = sGeo[k];
        const float z = fmaf(cx, g.x, fmaf(cy, g.y, ta[k]));
        h0[k] = silu_f(z);
    }
    float e = ab2[0];
#pragma unroll 4
    for (int k = 0; k < HH; k++) {
        float a0 = sB1[k], a1 = 0.f, a2 = 0.f, a3 = 0.f;
#pragma unroll
        for (int j4 = 0; j4 < 16; j4 += 4) {
            const float4 w0 = *reinterpret_cast<const float4*>(&sW1T[k * HH + (j4 + 0) * 4]);
            const float4 w1 = *reinterpret_cast<const float4*>(&sW1T[k * HH + (j4 + 1) * 4]);
            const float4 w2 = *reinterpret_cast<const float4*>(&sW1T[k * HH + (j4 + 2) * 4]);
            const float4 w3 = *reinterpret_cast<const float4*>(&sW1T[k * HH + (j4 + 3) * 4]);
            a0 = fmaf(h0[(j4+0)*4+0], w0.x, a0); a0 = fmaf(h0[(j4+0)*4+1], w0.y, a0);
            a0 = fmaf(h0[(j4+0)*4+2], w0.z, a0); a0 = fmaf(h0[(j4+0)*4+3], w0.w, a0);
            a1 = fmaf(h0[(j4+1)*4+0], w1.x, a1); a1 = fmaf(h0[(j4+1)*4+1], w1.y, a1);
            a1 = fmaf(h0[(j4+1)*4+2], w1.z, a1); a1 = fmaf(h0[(j4+1)*4+3], w1.w, a1);
            a2 = fmaf(h0[(j4+2)*4+0], w2.x, a2); a2 = fmaf(h0[(j4+2)*4+1], w2.y, a2);
            a2 = fmaf(h0[(j4+2)*4+2], w2.z, a2); a2 = fmaf(h0[(j4+2)*4+3], w2.w, a2);
            a3 = fmaf(h0[(j4+3)*4+0], w3.x, a3); a3 = fmaf(h0[(j4+3)*4+1], w3.y, a3);
            a3 = fmaf(h0[(j4+3)*4+2], w3.z, a3); a3 = fmaf(h0[(j4+3)*4+3], w3.w, a3);
        }
        const float z1 = (a0 + a1) + (a2 + a3);
        e = fmaf(silu_f(z1), sW2[k], e);
    }

    sRed[tid] = e;
    __syncthreads();
    for (int s = 128; s > 0; s >>= 1) {
        if (tid < s) sRed[tid] += sRed[tid + s];
        __syncthreads();
    }
    if (tid == 0) g_atomPart[b * 4 + blockIdx.x] = sRed[0];
}

// ---------------- pair channel ----------------
__global__ __launch_bounds__(256, 2)
void pair_kernel(const int* __restrict__ species,
                 const float* __restrict__ ef,
                 const float* __restrict__ pW0,
                 const float* __restrict__ pW1,
                 const float* __restrict__ pb1,
                 const float* __restrict__ pW2,
                 const float* __restrict__ pb2) {
    __shared__ float sW1T[HH * HH];         // [k][j]
    __shared__ float sTcomb[16 * 65];       // (si,sj) combined base, padded stride
    __shared__ float4 sGeo[HH];             // pW0 rows 0..3 per k
    __shared__ float sB1[HH], sW2[HH];
    __shared__ float2 sCpI[NT], sCpJ[NT];
    __shared__ int   sSpI[NT], sSpJ[NT];
    __shared__ float sRed[256];

    const int tid = threadIdx.x;
    const int b = blockIdx.y;

    // decode triangular tile index -> (ti, tj), ti <= tj
    int rem = blockIdx.x, ti = 0;
    while (rem >= NT - ti) { rem -= (NT - ti); ti++; }
    const int tj = ti + rem;

    for (int idx = tid; idx < HH * HH; idx += 256) {
        const int j = idx >> 6, k = idx & 63;
        sW1T[k * HH + j] = pW1[idx];
    }
    for (int idx = tid; idx < 16 * HH; idx += 256) {
        const int c = idx >> 6, k = idx & 63;
        sTcomb[c * 65 + k] = g_Pbase[b * HH + k]
                           + g_Tpi[(c >> 2) * HH + k]
                           + g_Tpj[(c & 3) * HH + k];
    }
    if (tid < HH) {
        sGeo[tid] = make_float4(pW0[0 * HH + tid], pW0[1 * HH + tid],
                                pW0[2 * HH + tid], pW0[3 * HH + tid]);
        sB1[tid] = pb1[tid];
        sW2[tid] = pW2[tid];
    }
    if (tid < NT) {
        const int gi = ti * NT + tid;
        sCpI[tid] = make_float2(g_cp[(b * NN + gi) * 2], g_cp[(b * NN + gi) * 2 + 1]);
        sSpI[tid] = species[b * NN + gi];
    } else if (tid < 2 * NT) {
        const int t = tid - NT;
        const int gj = tj * NT + t;
        sCpJ[t] = make_float2(g_cp[(b * NN + gj) * 2], g_cp[(b * NN + gj) * 2 + 1]);
        sSpJ[t] = species[b * NN + gj];
    }
    __syncthreads();

    const float Ex = ef[b * 2], Ey = ef[b * 2 + 1];
    const float pb2v = pb2[0];

    float energy = 0.f;
#pragma unroll
    for (int q = 0; q < 4; q++) {
        const int p = tid + 256 * q;
        const int il = p >> 5, jl = p & 31;
        const int gi = ti * NT + il, gj = tj * NT + jl;
        if (gi >= gj) continue;   // only relevant on diagonal tiles

        const float2 ci = sCpI[il], cj = sCpJ[jl];
        const float rx = ci.x - cj.x, ry = ci.y - cj.y;
        const float d  = sqrtf(rx * rx + ry * ry);
        const float dm = fmaxf(d, 1e-12f);
        const float edu = (Ex * rx + Ey * ry) / dm;
        const float* tc = &sTcomb[(sSpI[il] * 4 + sSpJ[jl]) * 65];

        float h0[HH];
#pragma unroll
        for (int k = 0; k < HH; k++) {
            const float4 g = sGeo[k];
            float z = tc[k];
            z = fmaf(rx, g.x, z); z = fmaf(ry, g.y, z);
            z = fmaf(d,  g.z, z); z = fmaf(edu, g.w, z);
            h0[k] = silu_f(z);
        }

        float e = pb2v;
#pragma unroll 4
        for (int k = 0; k < HH; k++) {
            float a0 = sB1[k], a1 = 0.f, a2 = 0.f, a3 = 0.f;
#pragma unroll
            for (int j4 = 0; j4 < 16; j4 += 4) {
                const float4 w0 = *reinterpret_cast<const float4*>(&sW1T[k * HH + (j4 + 0) * 4]);
                const float4 w1 = *reinterpret_cast<const float4*>(&sW1T[k * HH + (j4 + 1) * 4]);
                const float4 w2 = *reinterpret_cast<const float4*>(&sW1T[k * HH + (j4 + 2) * 4]);
                const float4 w3 = *reinterpret_cast<const float4*>(&sW1T[k * HH + (j4 + 3) * 4]);
                a0 = fmaf(h0[(j4+0)*4+0], w0.x, a0); a0 = fmaf(h0[(j4+0)*4+1], w0.y, a0);
                a0 = fmaf(h0[(j4+0)*4+2], w0.z, a0); a0 = fmaf(h0[(j4+0)*4+3], w0.w, a0);
                a1 = fmaf(h0[(j4+1)*4+0], w1.x, a1); a1 = fmaf(h0[(j4+1)*4+1], w1.y, a1);
                a1 = fmaf(h0[(j4+1)*4+2], w1.z, a1); a1 = fmaf(h0[(j4+1)*4+3], w1.w, a1);
                a2 = fmaf(h0[(j4+2)*4+0], w2.x, a2); a2 = fmaf(h0[(j4+2)*4+1], w2.y, a2);
                a2 = fmaf(h0[(j4+2)*4+2], w2.z, a2); a2 = fmaf(h0[(j4+2)*4+3], w2.w, a2);
                a3 = fmaf(h0[(j4+3)*4+0], w3.x, a3); a3 = fmaf(h0[(j4+3)*4+1], w3.y, a3);
                a3 = fmaf(h0[(j4+3)*4+2], w3.z, a3); a3 = fmaf(h0[(j4+3)*4+3], w3.w, a3);
            }
            const float z1 = (a0 + a1) + (a2 + a3);
            e = fmaf(silu_f(z1), sW2[k], e);
        }
        energy += e;
    }

    sRed[tid] = energy;
    __syncthreads();
    for (int s = 128; s > 0; s >>= 1) {
        if (tid < s) sRed[tid] += sRed[tid + s];
        __syncthreads();
    }
    if (tid == 0) g_pairPart[b * NTRI + blockIdx.x] = sRed[0];
}

// ---------------- deterministic fixed-order finalize ----------------
__global__ void finalize_kernel(float* __restrict__ out) {
    const int b = threadIdx.x;
    if (b < BB) {
        float s = 0.f;
        for (int t = 0; t < NTRI; t++) s += g_pairPart[b * NTRI + t];
        for (int c = 0; c < 4; c++)    s += g_atomPart[b * 4 + c];
        out[b] = s;
    }
}

// ---------------- launch ----------------
extern "C" void kernel_launch(void* const* d_in, const int* in_sizes, int n_in,
                              void* d_out, int out_size) {
    const float* positions = (const float*)d_in[0];
    const int*   species   = (const int*)d_in[1];
    const float* efield    = (const float*)d_in[2];
    const float* embed     = (const float*)d_in[3];
    const float* aW0 = (const float*)d_in[4];
    const float* ab0 = (const float*)d_in[5];
    const float* aW1 = (const float*)d_in[6];
    const float* ab1 = (const float*)d_in[7];
    const float* aW2 = (const float*)d_in[8];
    const float* ab2 = (const float*)d_in[9];
    const float* pW0 = (const float*)d_in[10];
    const float* pb0 = (const float*)d_in[11];
    const float* pW1 = (const float*)d_in[12];
    const float* pb1 = (const float*)d_in[13];
    const float* pW2 = (const float*)d_in[14];
    const float* pb2 = (const float*)d_in[15];
    float* out = (float*)d_out;

    prep_kernel<<<1, 256>>>(positions, efield, embed, aW0, ab0, pW0, pb0);
    atom_kernel<<<dim3(4, BB), 256>>>(species, aW0, aW1, ab1, aW2, ab2);
    pair_kernel<<<dim3(NTRI, BB), 256>>>(species, efield, pW0, pW1, pb1, pW2, pb2);
    finalize_kernel<<<1, 32>>>(out);
}

// round 3
// speedup vs baseline: 1.4524x; 1.4524x over previous
#include <cuda_runtime.h>
#include <math.h>

// Problem constants (fixed shapes)
#define BB 4
#define NN 1024
#define EE 16
#define SS 4
#define HH 64          // AH == PH == 64
#define NT 32          // tiles per dimension (N/32)
#define NTRI (NT*(NT+1)/2)   // 528 triangular tiles per batch
#define NBLK (NTRI*4)        // 4 sub-tiles per triangular tile

typedef unsigned long long u64;

// ---------------- device scratch (no allocations allowed) ----------------
__device__ float g_cp[BB * NN * 2];        // centered positions
__device__ float g_Tatom[SS * HH];         // embed @ aW0[5:21]
__device__ float g_Tpi[SS * HH];           // embed @ pW0[5:21]
__device__ float g_Tpj[SS * HH];           // embed @ pW0[21:37]
__device__ float g_ACbase[BB * HH];        // Ex*aW0[2]+Ey*aW0[3]+en*aW0[4]+ab0
__device__ float g_Pbase[BB * HH];         // en*pW0[4]+pb0
__device__ float g_pairPart[BB * NBLK];    // per-block pair partial sums
__device__ float g_atomPart[BB * 4];       // per-block atom partial sums

// ---------------- f32x2 helpers ----------------
__device__ __forceinline__ u64 pk2(float a, float b) {
    u64 r; asm("mov.b64 %0, {%1, %2};" : "=l"(r) : "f"(a), "f"(b)); return r;
}
__device__ __forceinline__ u64 fma2(u64 a, u64 b, u64 c) {
    u64 d; asm("fma.rn.f32x2 %0, %1, %2, %3;" : "=l"(d) : "l"(a), "l"(b), "l"(c)); return d;
}
__device__ __forceinline__ void upk2(u64 v, float& x, float& y) {
    asm("mov.b64 {%0, %1}, %2;" : "=f"(x), "=f"(y) : "l"(v));
}

__device__ __forceinline__ float silu_f(float x) {
    const float t = __expf(-x);
    return __fdividef(x, 1.0f + t);
}

// ---------------- prep: means, cp, tables ----------------
__global__ void prep_kernel(const float* __restrict__ pos,
                            const float* __restrict__ ef,
                            const float* __restrict__ embed,
                            const float* __restrict__ aW0,
                            const float* __restrict__ ab0,
                            const float* __restrict__ pW0,
                            const float* __restrict__ pb0) {
    const int tid = threadIdx.x; // 256 threads
    __shared__ float sx_[256], sy_[256];

    for (int b = 0; b < BB; b++) {
        float sx = 0.f, sy = 0.f;
        for (int n = tid; n < NN; n += 256) {
            sx += pos[(b * NN + n) * 2 + 0];
            sy += pos[(b * NN + n) * 2 + 1];
        }
        sx_[tid] = sx; sy_[tid] = sy;
        __syncthreads();
        for (int s = 128; s > 0; s >>= 1) {
            if (tid < s) { sx_[tid] += sx_[tid + s]; sy_[tid] += sy_[tid + s]; }
            __syncthreads();
        }
        const float mx = sx_[0] * (1.f / NN);
        const float my = sy_[0] * (1.f / NN);
        for (int n = tid; n < NN; n += 256) {
            g_cp[(b * NN + n) * 2 + 0] = pos[(b * NN + n) * 2 + 0] - mx;
            g_cp[(b * NN + n) * 2 + 1] = pos[(b * NN + n) * 2 + 1] - my;
        }
        __syncthreads();
    }

    // species tables: 256 entries total, one per thread
    {
        const int s = tid >> 6, k = tid & 63;
        float ta = 0.f, tpi = 0.f, tpj = 0.f;
#pragma unroll
        for (int e = 0; e < EE; e++) {
            const float em = embed[s * EE + e];
            ta  += em * aW0[(5 + e) * HH + k];
            tpi += em * pW0[(5 + e) * HH + k];
            tpj += em * pW0[(21 + e) * HH + k];
        }
        g_Tatom[tid] = ta; g_Tpi[tid] = tpi; g_Tpj[tid] = tpj;
    }
    // per-batch base rows: 256 entries (BB*HH)
    {
        const int b = tid >> 6, k = tid & 63;
        const float Ex = ef[b * 2], Ey = ef[b * 2 + 1];
        const float en = sqrtf(Ex * Ex + Ey * Ey);
        g_ACbase[tid] = Ex * aW0[2 * HH + k] + Ey * aW0[3 * HH + k]
                      + en * aW0[4 * HH + k] + ab0[k];
        g_Pbase[tid]  = en * pW0[4 * HH + k] + pb0[k];
    }
}

// ---------------- atom channel (tiny: 0.2% of work) ----------------
__global__ __launch_bounds__(256, 2)
void atom_kernel(const int* __restrict__ species,
                 const float* __restrict__ aW0,
                 const float* __restrict__ aW1,
                 const float* __restrict__ ab1,
                 const float* __restrict__ aW2,
                 const float* __restrict__ ab2) {
    __shared__ __align__(16) float sW1[HH * HH];   // [j][k] original layout
    __shared__ float sTA[SS * 65];
    __shared__ float2 sGeo[HH];
    __shared__ __align__(16) float sB1[HH];
    __shared__ float sW2[HH];
    __shared__ float sRed[256];

    const int tid = threadIdx.x;
    const int b = blockIdx.y;
    const int n = blockIdx.x * 256 + tid;

    for (int idx = tid; idx < HH * HH; idx += 256) sW1[idx] = aW1[idx];
    for (int idx = tid; idx < SS * HH; idx += 256) {
        const int s = idx >> 6, k = idx & 63;
        sTA[s * 65 + k] = g_ACbase[b * HH + k] + g_Tatom[s * HH + k];
    }
    if (tid < HH) {
        sGeo[tid] = make_float2(aW0[tid], aW0[HH + tid]);
        sB1[tid] = ab1[tid];
        sW2[tid] = aW2[tid];
    }
    __syncthreads();

    const float cx = g_cp[(b * NN + n) * 2 + 0];
    const float cy = g_cp[(b * NN + n) * 2 + 1];
    const int sp = species[b * NN + n];
    const float* ta = &sTA[sp * 65];

    float h0[HH];
#pragma unroll
    for (int k = 0; k < HH; k++) {
        const float2 g = sGeo[k];
        const float z = fmaf(cx, g.x, fmaf(cy, g.y, ta[k]));
        h0[k] = silu_f(z);
    }

    float e = ab2[0];
#pragma unroll
    for (int kc = 0; kc < HH; kc += 32) {
        u64 acc[16];
        const u64* b1p = (const u64*)&sB1[kc];
#pragma unroll
        for (int m = 0; m < 16; m++) acc[m] = b1p[m];
#pragma unroll
        for (int j = 0; j < HH; j++) {
            const u64 hj = pk2(h0[j], h0[j]);
            const ulonglong2* w = (const ulonglong2*)&sW1[j * HH + kc];
#pragma unroll
            for (int m = 0; m < 8; m++) {
                const ulonglong2 ww = w[m];
                acc[2 * m + 0] = fma2(hj, ww.x, acc[2 * m + 0]);
                acc[2 * m + 1] = fma2(hj, ww.y, acc[2 * m + 1]);
            }
        }
#pragma unroll
        for (int m = 0; m < 16; m++) {
            float z0, z1;
            upk2(acc[m], z0, z1);
            e = fmaf(silu_f(z0), sW2[kc + 2 * m + 0], e);
            e = fmaf(silu_f(z1), sW2[kc + 2 * m + 1], e);
        }
    }

    sRed[tid] = e;
    __syncthreads();
    for (int s = 128; s > 0; s >>= 1) {
        if (tid < s) sRed[tid] += sRed[tid + s];
        __syncthreads();
    }
    if (tid == 0) g_atomPart[b * 4 + blockIdx.x] = sRed[0];
}

// ---------------- pair channel: f32x2 register-tiled ----------------
__global__ __launch_bounds__(256, 2)
void pair_kernel(const int* __restrict__ species,
                 const float* __restrict__ ef,
                 const float* __restrict__ pW0,
                 const float* __restrict__ pW1,
                 const float* __restrict__ pb1,
                 const float* __restrict__ pW2,
                 const float* __restrict__ pb2) {
    __shared__ __align__(16) float sW1[HH * HH];   // [j][k] original layout
    __shared__ float sTcomb[16 * 65];              // (si,sj) combined base, padded
    __shared__ float4 sGeo[HH];                    // pW0 rows 0..3 per k
    __shared__ __align__(16) float sB1[HH];
    __shared__ float sW2[HH];
    __shared__ float2 sCpI[NT], sCpJ[8];
    __shared__ int   sSpI[NT], sSpJ[8];
    __shared__ float sRed[256];

    const int tid = threadIdx.x;
    const int b = blockIdx.y;

    // decode sub-tile: blockIdx.x = tri_tile*4 + q
    const int t4 = blockIdx.x;
    int rem = t4 >> 2, ti = 0;
    while (rem >= NT - ti) { rem -= (NT - ti); ti++; }
    const int tj = ti + rem;
    const int q = t4 & 3;

    for (int idx = tid; idx < HH * HH; idx += 256) sW1[idx] = pW1[idx];
    for (int idx = tid; idx < 16 * HH; idx += 256) {
        const int c = idx >> 6, k = idx & 63;
        sTcomb[c * 65 + k] = g_Pbase[b * HH + k]
                           + g_Tpi[(c >> 2) * HH + k]
                           + g_Tpj[(c & 3) * HH + k];
    }
    if (tid < HH) {
        sGeo[tid] = make_float4(pW0[0 * HH + tid], pW0[1 * HH + tid],
                                pW0[2 * HH + tid], pW0[3 * HH + tid]);
        sB1[tid] = pb1[tid];
        sW2[tid] = pW2[tid];
    }
    if (tid < NT) {
        const int gi = ti * NT + tid;
        sCpI[tid] = make_float2(g_cp[(b * NN + gi) * 2], g_cp[(b * NN + gi) * 2 + 1]);
        sSpI[tid] = species[b * NN + gi];
    } else if (tid < NT + 8) {
        const int t = tid - NT;
        const int gj = tj * NT + q * 8 + t;
        sCpJ[t] = make_float2(g_cp[(b * NN + gj) * 2], g_cp[(b * NN + gj) * 2 + 1]);
        sSpJ[t] = species[b * NN + gj];
    }
    __syncthreads();

    const float Ex = ef[b * 2], Ey = ef[b * 2 + 1];

    // one slot per thread: il = tid>>3 (0..31), jl = q*8 + (tid&7)
    const int il = tid >> 3, jlq = tid & 7;
    const int gi = ti * NT + il, gj = tj * NT + q * 8 + jlq;

    const float2 ci = sCpI[il], cj = sCpJ[jlq];
    const float rx = ci.x - cj.x, ry = ci.y - cj.y;
    const float d  = sqrtf(rx * rx + ry * ry);
    const float dm = fmaxf(d, 1e-12f);
    const float edu = __fdividef(fmaf(Ex, rx, Ey * ry), dm);
    const float* tc = &sTcomb[(sSpI[il] * 4 + sSpJ[jlq]) * 65];

    // layer 0
    float h0[HH];
#pragma unroll
    for (int k = 0; k < HH; k++) {
        const float4 g = sGeo[k];
        float z = tc[k];
        z = fmaf(rx, g.x, z); z = fmaf(ry, g.y, z);
        z = fmaf(d,  g.z, z); z = fmaf(edu, g.w, z);
        h0[k] = silu_f(z);
    }

    // layer 1 (f32x2, k-packed) + layer 2
    float e = pb2[0];
#pragma unroll
    for (int kc = 0; kc < HH; kc += 32) {
        u64 acc[16];
        const u64* b1p = (const u64*)&sB1[kc];
#pragma unroll
        for (int m = 0; m < 16; m++) acc[m] = b1p[m];
#pragma unroll
        for (int j = 0; j < HH; j++) {
            const u64 hj = pk2(h0[j], h0[j]);
            const ulonglong2* w = (const ulonglong2*)&sW1[j * HH + kc];
#pragma unroll
            for (int m = 0; m < 8; m++) {
                const ulonglong2 ww = w[m];
                acc[2 * m + 0] = fma2(hj, ww.x, acc[2 * m + 0]);
                acc[2 * m + 1] = fma2(hj, ww.y, acc[2 * m + 1]);
            }
        }
#pragma unroll
        for (int m = 0; m < 16; m++) {
            float z0, z1;
            upk2(acc[m], z0, z1);
            e = fmaf(silu_f(z0), sW2[kc + 2 * m + 0], e);
            e = fmaf(silu_f(z1), sW2[kc + 2 * m + 1], e);
        }
    }

    // branchless mask for diagonal / lower-triangular slots
    const float energy = (gi < gj) ? e : 0.0f;

    sRed[tid] = energy;
    __syncthreads();
    for (int s = 128; s > 0; s >>= 1) {
        if (tid < s) sRed[tid] += sRed[tid + s];
        __syncthreads();
    }
    if (tid == 0) g_pairPart[b * NBLK + blockIdx.x] = sRed[0];
}

// ---------------- deterministic parallel finalize ----------------
__global__ void finalize_kernel(float* __restrict__ out) {
    __shared__ float red[256];
    const int tid = threadIdx.x;
    const int b = tid >> 6, lane = tid & 63;
    float s = 0.f;
    for (int t = lane; t < NBLK; t += 64) s += g_pairPart[b * NBLK + t];
    if (lane < 4) s += g_atomPart[b * 4 + lane];
    red[tid] = s;
    __syncthreads();
    for (int st = 32; st > 0; st >>= 1) {
        if (lane < st) red[tid] += red[tid + st];
        __syncthreads();
    }
    if (lane == 0) out[b] = red[tid];
}

// ---------------- launch ----------------
extern "C" void kernel_launch(void* const* d_in, const int* in_sizes, int n_in,
                              void* d_out, int out_size) {
    const float* positions = (const float*)d_in[0];
    const int*   species   = (const int*)d_in[1];
    const float* efield    = (const float*)d_in[2];
    const float* embed     = (const float*)d_in[3];
    const float* aW0 = (const float*)d_in[4];
    const float* ab0 = (const float*)d_in[5];
    const float* aW1 = (const float*)d_in[6];
    const float* ab1 = (const float*)d_in[7];
    const float* aW2 = (const float*)d_in[8];
    const float* ab2 = (const float*)d_in[9];
    const float* pW0 = (const float*)d_in[10];
    const float* pb0 = (const float*)d_in[11];
    const float* pW1 = (const float*)d_in[12];
    const float* pb1 = (const float*)d_in[13];
    const float* pW2 = (const float*)d_in[14];
    const float* pb2 = (const float*)d_in[15];
    float* out = (float*)d_out;

    prep_kernel<<<1, 256>>>(positions, efield, embed, aW0, ab0, pW0, pb0);
    atom_kernel<<<dim3(4, BB), 256>>>(species, aW0, aW1, ab1, aW2, ab2);
    pair_kernel<<<dim3(NBLK, BB), 256>>>(species, efield, pW0, pW1, pb1, pW2, pb2);
    finalize_kernel<<<1, 256>>>(out);
}

// round 7
// speedup vs baseline: 2.5537x; 1.7583x over previous
#include <cuda_runtime.h>
#include <cuda_bf16.h>
#include <math.h>
#include <stdint.h>

// Problem constants (fixed shapes)
#define BB 4
#define NN 1024
#define EE 16
#define SS 4
#define HH 64          // AH == PH == 64
#define NT 32          // tiles per dimension (N/32)
#define NTRI 528       // triangular 32x32 tiles per batch
#define TILES_PER_B (NTRI * 4)       // 2112 sub-tiles (8i x 32j = 256 pairs)
#define TOT_TILES (BB * TILES_PER_B) // 8448

#define MAX_CTAS 160
#define PAIRW_SLOTS (MAX_CTAS * 8)   // per-warp partials

// smem pool layout (bytes)
#define STRIDE_B 144                  // 72 bf16 per row: conflict-free ldmatrix
#define OFF_BHI   0
#define OFF_BLO   (OFF_BHI + HH * STRIDE_B)          // 9216
#define OFF_A     (OFF_BLO + HH * STRIDE_B)          // 18432
#define A_WARP_BYTES (2 * 32 * STRIDE_B)             // hi + lo per warp = 9216
#define OFF_TCOMB (OFF_A + 8 * A_WARP_BYTES)         // 92160
#define OFF_GEO   (OFF_TCOMB + BB * 16 * 65 * 4)     // 108800
#define OFF_B1    (OFF_GEO + HH * 16)                // 109824
#define OFF_W2    (OFF_B1 + HH * 4)                  // 110080
#define SMEM_BYTES (OFF_W2 + HH * 4)                 // 110336

typedef unsigned long long u64;

// ---------------- device scratch (no allocations allowed) ----------------
__device__ float g_cp[BB * NN * 2];
__device__ float g_Tatom[SS * HH];
__device__ float g_Tpi[SS * HH];
__device__ float g_Tpj[SS * HH];
__device__ float g_ACbase[BB * HH];
__device__ float g_Pbase[BB * HH];
__device__ float g_pairW[PAIRW_SLOTS * BB];   // zero-init; unlaunched slots stay 0
__device__ float g_atomPart[BB * 4];

// ---------------- small helpers ----------------
__device__ __forceinline__ u64 pk2(float a, float b) {
    u64 r; asm("mov.b64 %0, {%1, %2};" : "=l"(r) : "f"(a), "f"(b)); return r;
}
__device__ __forceinline__ u64 fma2(u64 a, u64 b, u64 c) {
    u64 d; asm("fma.rn.f32x2 %0, %1, %2, %3;" : "=l"(d) : "l"(a), "l"(b), "l"(c)); return d;
}
__device__ __forceinline__ void upk2(u64 v, float& x, float& y) {
    asm("mov.b64 {%0, %1}, %2;" : "=f"(x), "=f"(y) : "l"(v));
}
__device__ __forceinline__ float silu_f(float x) {
    const float t = __expf(-x);
    return __fdividef(x, 1.0f + t);
}
__device__ __forceinline__ uint32_t smem_u32(const void* p) {
    uint32_t a;
    asm("{ .reg .u64 tmp; cvta.to.shared.u64 tmp, %1; cvt.u32.u64 %0, tmp; }"
        : "=r"(a) : "l"(p));
    return a;
}
// bf16x2 pack: word = {hi = a(odd k), lo = b(even k)}
__device__ __forceinline__ uint32_t packbf2(float odd, float even) {
    uint32_t w;
    asm("cvt.rn.bf16x2.f32 %0, %1, %2;" : "=r"(w) : "f"(odd), "f"(even));
    return w;
}
__device__ __forceinline__ void ldsm4(uint32_t* r, uint32_t addr) {
    asm volatile("ldmatrix.sync.aligned.m8n8.x4.shared.b16 {%0,%1,%2,%3}, [%4];"
                 : "=r"(r[0]), "=r"(r[1]), "=r"(r[2]), "=r"(r[3]) : "r"(addr));
}
__device__ __forceinline__ void mma_bf16(float* c, const uint32_t* a, const uint32_t* b) {
    asm volatile(
        "mma.sync.aligned.m16n8k16.row.col.f32.bf16.bf16.f32 "
        "{%0,%1,%2,%3}, {%4,%5,%6,%7}, {%8,%9}, {%0,%1,%2,%3};"
        : "+f"(c[0]), "+f"(c[1]), "+f"(c[2]), "+f"(c[3])
        : "r"(a[0]), "r"(a[1]), "r"(a[2]), "r"(a[3]), "r"(b[0]), "r"(b[1]));
}

// ---------------- prep: means, cp, tables ----------------
__global__ void prep_kernel(const float* __restrict__ pos,
                            const float* __restrict__ ef,
                            const float* __restrict__ embed,
                            const float* __restrict__ aW0,
                            const float* __restrict__ ab0,
                            const float* __restrict__ pW0,
                            const float* __restrict__ pb0) {
    const int tid = threadIdx.x; // 256 threads
    __shared__ float sx_[256], sy_[256];

    for (int b = 0; b < BB; b++) {
        float sx = 0.f, sy = 0.f;
        for (int n = tid; n < NN; n += 256) {
            sx += pos[(b * NN + n) * 2 + 0];
            sy += pos[(b * NN + n) * 2 + 1];
        }
        sx_[tid] = sx; sy_[tid] = sy;
        __syncthreads();
        for (int s = 128; s > 0; s >>= 1) {
            if (tid < s) { sx_[tid] += sx_[tid + s]; sy_[tid] += sy_[tid + s]; }
            __syncthreads();
        }
        const float mx = sx_[0] * (1.f / NN);
        const float my = sy_[0] * (1.f / NN);
        for (int n = tid; n < NN; n += 256) {
            g_cp[(b * NN + n) * 2 + 0] = pos[(b * NN + n) * 2 + 0] - mx;
            g_cp[(b * NN + n) * 2 + 1] = pos[(b * NN + n) * 2 + 1] - my;
        }
        __syncthreads();
    }
    {
        const int s = tid >> 6, k = tid & 63;
        float ta = 0.f, tpi = 0.f, tpj = 0.f;
#pragma unroll
        for (int e = 0; e < EE; e++) {
            const float em = embed[s * EE + e];
            ta  += em * aW0[(5 + e) * HH + k];
            tpi += em * pW0[(5 + e) * HH + k];
            tpj += em * pW0[(21 + e) * HH + k];
        }
        g_Tatom[tid] = ta; g_Tpi[tid] = tpi; g_Tpj[tid] = tpj;
    }
    {
        const int b = tid >> 6, k = tid & 63;
        const float Ex = ef[b * 2], Ey = ef[b * 2 + 1];
        const float en = sqrtf(Ex * Ex + Ey * Ey);
        g_ACbase[tid] = Ex * aW0[2 * HH + k] + Ey * aW0[3 * HH + k]
                      + en * aW0[4 * HH + k] + ab0[k];
        g_Pbase[tid]  = en * pW0[4 * HH + k] + pb0[k];
    }
}

// ---------------- atom channel (tiny; known-good f32x2 version) ----------------
__global__ __launch_bounds__(256, 2)
void atom_kernel(const int* __restrict__ species,
                 const float* __restrict__ aW0,
                 const float* __restrict__ aW1,
                 const float* __restrict__ ab1,
                 const float* __restrict__ aW2,
                 const float* __restrict__ ab2) {
    __shared__ __align__(16) float sW1[HH * HH];
    __shared__ float sTA[SS * 65];
    __shared__ float2 sGeo[HH];
    __shared__ __align__(16) float sB1[HH];
    __shared__ float sW2[HH];
    __shared__ float sRed[256];

    const int tid = threadIdx.x;
    const int b = blockIdx.y;
    const int n = blockIdx.x * 256 + tid;

    for (int idx = tid; idx < HH * HH; idx += 256) sW1[idx] = aW1[idx];
    for (int idx = tid; idx < SS * HH; idx += 256) {
        const int s = idx >> 6, k = idx & 63;
        sTA[s * 65 + k] = g_ACbase[b * HH + k] + g_Tatom[s * HH + k];
    }
    if (tid < HH) {
        sGeo[tid] = make_float2(aW0[tid], aW0[HH + tid]);
        sB1[tid] = ab1[tid];
        sW2[tid] = aW2[tid];
    }
    __syncthreads();

    const float cx = g_cp[(b * NN + n) * 2 + 0];
    const float cy = g_cp[(b * NN + n) * 2 + 1];
    const int sp = species[b * NN + n];
    const float* ta = &sTA[sp * 65];

    float h0[HH];
#pragma unroll
    for (int k = 0; k < HH; k++) {
        const float2 g = sGeo[k];
        const float z = fmaf(cx, g.x, fmaf(cy, g.y, ta[k]));
        h0[k] = silu_f(z);
    }

    float e = ab2[0];
#pragma unroll
    for (int kc = 0; kc < HH; kc += 32) {
        u64 acc[16];
        const u64* b1p = (const u64*)&sB1[kc];
#pragma unroll
        for (int m = 0; m < 16; m++) acc[m] = b1p[m];
#pragma unroll
        for (int j = 0; j < HH; j++) {
            const u64 hj = pk2(h0[j], h0[j]);
            const ulonglong2* w = (const ulonglong2*)&sW1[j * HH + kc];
#pragma unroll
            for (int m = 0; m < 8; m++) {
                const ulonglong2 ww = w[m];
                acc[2 * m + 0] = fma2(hj, ww.x, acc[2 * m + 0]);
                acc[2 * m + 1] = fma2(hj, ww.y, acc[2 * m + 1]);
            }
        }
#pragma unroll
        for (int m = 0; m < 16; m++) {
            float z0, z1;
            upk2(acc[m], z0, z1);
            e = fmaf(silu_f(z0), sW2[kc + 2 * m + 0], e);
            e = fmaf(silu_f(z1), sW2[kc + 2 * m + 1], e);
        }
    }

    sRed[tid] = e;
    __syncthreads();
    for (int s = 128; s > 0; s >>= 1) {
        if (tid < s) sRed[tid] += sRed[tid + s];
        __syncthreads();
    }
    if (tid == 0) g_atomPart[b * 4 + blockIdx.x] = sRed[0];
}

// ---------------- pair channel: persistent warp-level HMMA kernel ----------------
__global__ __launch_bounds__(256, 1)
void pair_mma_kernel(const int* __restrict__ species,
                     const float* __restrict__ ef,
                     const float* __restrict__ pW0,
                     const float* __restrict__ pW1,
                     const float* __restrict__ pb1,
                     const float* __restrict__ pW2,
                     const float* __restrict__ pb2) {
    extern __shared__ __align__(16) char smem[];
    float*  sTcomb = (float*)(smem + OFF_TCOMB);
    float4* sGeo   = (float4*)(smem + OFF_GEO);
    float*  sB1    = (float*)(smem + OFF_B1);
    float*  sW2    = (float*)(smem + OFF_W2);

    const int tid  = threadIdx.x;
    const int wid  = tid >> 5;
    const int lane = tid & 31;

    // ---- init staged weights: B = W1^T (rows n, cols k=j), bf16 hi + residual lo
    for (int idx = tid; idx < HH * HH; idx += 256) {
        const int n = idx >> 6, j = idx & 63;
        const float w = pW1[j * HH + n];
        const __nv_bfloat16 wh = __float2bfloat16_rn(w);
        const float wl = w - __bfloat162float(wh);
        *(__nv_bfloat16*)(smem + OFF_BHI + n * STRIDE_B + j * 2) = wh;
        *(__nv_bfloat16*)(smem + OFF_BLO + n * STRIDE_B + j * 2) = __float2bfloat16_rn(wl);
    }
    for (int idx = tid; idx < BB * 16 * HH; idx += 256) {
        const int bc = idx >> 6, k = idx & 63;
        const int b = bc >> 4, c = bc & 15;
        sTcomb[bc * 65 + k] = g_Pbase[b * HH + k]
                            + g_Tpi[(c >> 2) * HH + k]
                            + g_Tpj[(c & 3) * HH + k];
    }
    if (tid < HH) {
        sGeo[tid] = make_float4(pW0[0 * HH + tid], pW0[1 * HH + tid],
                                pW0[2 * HH + tid], pW0[3 * HH + tid]);
        sB1[tid] = pb1[tid];
        sW2[tid] = pW2[tid];
    }
    __syncthreads();

    // per-thread epilogue constants: cols n = nt*8 + (lane&3)*2 + {0,1}
    float b1v[8][2], w2v[8][2];
#pragma unroll
    for (int nt = 0; nt < 8; nt++) {
        const int n0 = nt * 8 + (lane & 3) * 2;
        b1v[nt][0] = sB1[n0];     b1v[nt][1] = sB1[n0 + 1];
        w2v[nt][0] = sW2[n0];     w2v[nt][1] = sW2[n0 + 1];
    }
    const float pb2v = pb2[0];

    const uint32_t smem_base = smem_u32(smem);
    const uint32_t aw_hi = smem_base + OFF_A + wid * A_WARP_BYTES;
    const uint32_t aw_lo = aw_hi + 32 * STRIDE_B;
    const uint32_t bhi_u = smem_base + OFF_BHI;
    const uint32_t blo_u = smem_base + OFF_BLO;
    // ldmatrix lane addressing pieces
    const uint32_t lrow = lane & 15, lhalf = (lane >> 4) * 16;

    float bacc0 = 0.f, bacc1 = 0.f, bacc2 = 0.f, bacc3 = 0.f;

    for (int t = blockIdx.x; t < TOT_TILES; t += gridDim.x) {
        const int b = t / TILES_PER_B;
        const int tt = t - b * TILES_PER_B;
        const int tri = tt >> 2, sub = tt & 3;
        int rem = tri, ti = 0;
        while (rem >= NT - ti) { rem -= (NT - ti); ti++; }
        const int tj = ti + rem;

        const int il = sub * 8 + wid;           // warp's i row
        const int gi = ti * NT + il;
        const int gj = tj * NT + lane;          // lane's j (pair row = lane)

        const float2 ci = *(const float2*)&g_cp[(b * NN + gi) * 2];
        const float2 cj = *(const float2*)&g_cp[(b * NN + gj) * 2];
        const int si = species[b * NN + gi], sj = species[b * NN + gj];
        const float Ex = ef[b * 2], Ey = ef[b * 2 + 1];

        const float rx = ci.x - cj.x, ry = ci.y - cj.y;
        const float d = sqrtf(rx * rx + ry * ry);
        const float dm = fmaxf(d, 1e-12f);
        const float edu = __fdividef(fmaf(Ex, rx, Ey * ry), dm);
        const float* tc = &sTcomb[(b * 16 + si * 4 + sj) * 65];

        // ---- layer 0: compute h0, split bf16 hi/lo, stage row = lane
        __syncwarp();   // protect prior ldmatrix reads from overwrite
        {
            uint4* dh = (uint4*)(smem + OFF_A + wid * A_WARP_BYTES + lane * STRIDE_B);
            uint4* dl = (uint4*)((char*)dh + 32 * STRIDE_B);
#pragma unroll
            for (int q = 0; q < 8; q++) {
                uint32_t hw[4], lw[4];
#pragma unroll
                for (int c = 0; c < 4; c++) {
                    const int k0 = q * 8 + c * 2;
                    const float4 g0 = sGeo[k0], g1 = sGeo[k0 + 1];
                    float z0 = tc[k0], z1 = tc[k0 + 1];
                    z0 = fmaf(rx, g0.x, z0); z0 = fmaf(ry, g0.y, z0);
                    z0 = fmaf(d, g0.z, z0);  z0 = fmaf(edu, g0.w, z0);
                    z1 = fmaf(rx, g1.x, z1); z1 = fmaf(ry, g1.y, z1);
                    z1 = fmaf(d, g1.z, z1);  z1 = fmaf(edu, g1.w, z1);
                    const float h0 = silu_f(z0), h1 = silu_f(z1);
                    const uint32_t w = packbf2(h1, h0);
                    const __nv_bfloat162 bh = *(const __nv_bfloat162*)&w;
                    const float r0 = h0 - __bfloat162float(bh.x);
                    const float r1 = h1 - __bfloat162float(bh.y);
                    hw[c] = w;
                    lw[c] = packbf2(r1, r0);
                }
                dh[q] = make_uint4(hw[0], hw[1], hw[2], hw[3]);
                dl[q] = make_uint4(lw[0], lw[1], lw[2], lw[3]);
            }
        }
        __syncwarp();

        // ---- layer 1: 3-term compensated bf16 MMA: M32 x N64 x K64
        float acc[2][8][4];
#pragma unroll
        for (int mt = 0; mt < 2; mt++)
#pragma unroll
            for (int nt = 0; nt < 8; nt++)
#pragma unroll
                for (int c = 0; c < 4; c++) acc[mt][nt][c] = 0.f;

#pragma unroll
        for (int ks = 0; ks < 4; ks++) {
            const uint32_t koff = ks * 32 + lhalf;
            uint32_t ahi[2][4], alo[2][4];
#pragma unroll
            for (int mt = 0; mt < 2; mt++) {
                ldsm4(ahi[mt], aw_hi + (mt * 16 + lrow) * STRIDE_B + koff);
                ldsm4(alo[mt], aw_lo + (mt * 16 + lrow) * STRIDE_B + koff);
            }
            uint32_t bh[8][2], bl[8][2];
#pragma unroll
            for (int nq = 0; nq < 4; nq++) {
                uint32_t r[4];
                ldsm4(r, bhi_u + (nq * 16 + lrow) * STRIDE_B + koff);
                bh[2 * nq][0] = r[0]; bh[2 * nq][1] = r[2];
                bh[2 * nq + 1][0] = r[1]; bh[2 * nq + 1][1] = r[3];
                ldsm4(r, blo_u + (nq * 16 + lrow) * STRIDE_B + koff);
                bl[2 * nq][0] = r[0]; bl[2 * nq][1] = r[2];
                bl[2 * nq + 1][0] = r[1]; bl[2 * nq + 1][1] = r[3];
            }
#pragma unroll
            for (int mt = 0; mt < 2; mt++)
#pragma unroll
                for (int nt = 0; nt < 8; nt++) {
                    mma_bf16(acc[mt][nt], ahi[mt], bh[nt]);
                    mma_bf16(acc[mt][nt], ahi[mt], bl[nt]);
                    mma_bf16(acc[mt][nt], alo[mt], bh[nt]);
                }
        }

        // ---- epilogue: bias + silu + dot W2, mask, reduce
        float v = 0.f;
        int cnt = 0;
#pragma unroll
        for (int mt = 0; mt < 2; mt++) {
            const int p0 = mt * 16 + (lane >> 2);
            const int p1 = p0 + 8;
            float s0 = 0.f, s1 = 0.f;
#pragma unroll
            for (int nt = 0; nt < 8; nt++) {
                s0 = fmaf(silu_f(acc[mt][nt][0] + b1v[nt][0]), w2v[nt][0], s0);
                s0 = fmaf(silu_f(acc[mt][nt][1] + b1v[nt][1]), w2v[nt][1], s0);
                s1 = fmaf(silu_f(acc[mt][nt][2] + b1v[nt][0]), w2v[nt][0], s1);
                s1 = fmaf(silu_f(acc[mt][nt][3] + b1v[nt][1]), w2v[nt][1], s1);
            }
            const bool m0 = gi < (tj * NT + p0);
            const bool m1 = gi < (tj * NT + p1);
            v += (m0 ? s0 : 0.f) + (m1 ? s1 : 0.f);
            cnt += (int)m0 + (int)m1;
        }
        // sum the 4-thread column groups (rows shared by lanes with same lane>>2)
        v += __shfl_xor_sync(0xFFFFFFFFu, v, 1);
        v += __shfl_xor_sync(0xFFFFFFFFu, v, 2);
        v = ((lane & 3) == 0) ? fmaf(pb2v, (float)cnt, v) : 0.f;
        v += __shfl_xor_sync(0xFFFFFFFFu, v, 4);
        v += __shfl_xor_sync(0xFFFFFFFFu, v, 8);
        v += __shfl_xor_sync(0xFFFFFFFFu, v, 16);
        if (lane == 0) {
            if      (b == 0) bacc0 += v;
            else if (b == 1) bacc1 += v;
            else if (b == 2) bacc2 += v;
            else             bacc3 += v;
        }
    }

    if (lane == 0) {
        float* dst = &g_pairW[(blockIdx.x * 8 + wid) * BB];
        dst[0] = bacc0; dst[1] = bacc1; dst[2] = bacc2; dst[3] = bacc3;
    }
}

// ---------------- deterministic parallel finalize ----------------
__global__ void finalize_kernel(float* __restrict__ out) {
    __shared__ float red[256];
    const int tid = threadIdx.x;
    const int b = tid >> 6, lane = tid & 63;
    float s = 0.f;
    for (int i = lane; i < PAIRW_SLOTS; i += 64) s += g_pairW[i * BB + b];
    if (lane < 4) s += g_atomPart[b * 4 + lane];
    red[tid] = s;
    __syncthreads();
    for (int st = 32; st > 0; st >>= 1) {
        if (lane < st) red[tid] += red[tid + st];
        __syncthreads();
    }
    if (lane == 0) out[b] = red[tid];
}

// ---------------- launch ----------------
extern "C" void kernel_launch(void* const* d_in, const int* in_sizes, int n_in,
                              void* d_out, int out_size) {
    const float* positions = (const float*)d_in[0];
    const int*   species   = (const int*)d_in[1];
    const float* efield    = (const float*)d_in[2];
    const float* embed     = (const float*)d_in[3];
    const float* aW0 = (const float*)d_in[4];
    const float* ab0 = (const float*)d_in[5];
    const float* aW1 = (const float*)d_in[6];
    const float* ab1 = (const float*)d_in[7];
    const float* aW2 = (const float*)d_in[8];
    const float* ab2 = (const float*)d_in[9];
    const float* pW0 = (const float*)d_in[10];
    const float* pb0 = (const float*)d_in[11];
    const float* pW1 = (const float*)d_in[12];
    const float* pb1 = (const float*)d_in[13];
    const float* pW2 = (const float*)d_in[14];
    const float* pb2 = (const float*)d_in[15];
    float* out = (float*)d_out;

    int sms = 148;
    cudaDeviceGetAttribute(&sms, cudaDevAttrMultiProcessorCount, 0);
    int grid_pair = sms < MAX_CTAS ? sms : MAX_CTAS;

    cudaFuncSetAttribute(pair_mma_kernel,
                         cudaFuncAttributeMaxDynamicSharedMemorySize, SMEM_BYTES);

    prep_kernel<<<1, 256>>>(positions, efield, embed, aW0, ab0, pW0, pb0);
    atom_kernel<<<dim3(4, BB), 256>>>(species, aW0, aW1, ab1, aW2, ab2);
    pair_mma_kernel<<<grid_pair, 256, SMEM_BYTES>>>(species, efield, pW0, pW1, pb1, pW2, pb2);
    finalize_kernel<<<1, 256>>>(out);
}

// round 10
// speedup vs baseline: 3.0149x; 1.1806x over previous
#include <cuda_runtime.h>
#include <cuda_bf16.h>
#include <math.h>
#include <stdint.h>

// Problem constants (fixed shapes)
#define BB 4
#define NN 1024
#define EE 16
#define SS 4
#define HH 64          // AH == PH == 64
#define NT 32          // tiles per dimension (N/32)
#define NTRI 528       // triangular 32x32 tiles per batch
#define NTASKS (BB * NTRI * 32)      // 67584 warp-tasks (one i-row x 32 j)

#define MAX_CTAS 640
#define MAXW (MAX_CTAS * 4)          // 2560 warp slots

#define STRIDE_B 144                 // 72 bf16 per row: conflict-free ldmatrix
#define TC_STRIDE 66                 // even stride -> aligned float2

typedef unsigned long long u64;

// ---------------- device scratch (no allocations allowed) ----------------
__device__ float g_cp[BB * NN * 2];
__device__ float g_Tatom[SS * HH];
__device__ float g_Tpi[SS * HH];
__device__ float g_Tpj[SS * HH];
__device__ float g_ACbase[BB * HH];
__device__ float g_Pbase[BB * HH];
__device__ float g_pairW[BB * MAXW];   // zero-init; unlaunched slots stay 0
__device__ float g_atomPart[BB * 4];

// ---------------- small helpers ----------------
__device__ __forceinline__ u64 pk2(float a, float b) {
    u64 r; asm("mov.b64 %0, {%1, %2};" : "=l"(r) : "f"(a), "f"(b)); return r;
}
__device__ __forceinline__ u64 fma2(u64 a, u64 b, u64 c) {
    u64 d; asm("fma.rn.f32x2 %0, %1, %2, %3;" : "=l"(d) : "l"(a), "l"(b), "l"(c)); return d;
}
__device__ __forceinline__ void upk2(u64 v, float& x, float& y) {
    asm("mov.b64 {%0, %1}, %2;" : "=f"(x), "=f"(y) : "l"(v));
}
__device__ __forceinline__ float silu_f(float x) {
    const float t = __expf(-x);
    return __fdividef(x, 1.0f + t);
}
__device__ __forceinline__ uint32_t smem_u32(const void* p) {
    uint32_t a;
    asm("{ .reg .u64 tmp; cvta.to.shared.u64 tmp, %1; cvt.u32.u64 %0, tmp; }"
        : "=r"(a) : "l"(p));
    return a;
}
// bf16x2 pack: word = {hi = odd-k value, lo = even-k value}
__device__ __forceinline__ uint32_t packbf2(float odd, float even) {
    uint32_t w;
    asm("cvt.rn.bf16x2.f32 %0, %1, %2;" : "=r"(w) : "f"(odd), "f"(even));
    return w;
}
__device__ __forceinline__ void ldsm4(uint32_t* r, uint32_t addr) {
    asm volatile("ldmatrix.sync.aligned.m8n8.x4.shared.b16 {%0,%1,%2,%3}, [%4];"
                 : "=r"(r[0]), "=r"(r[1]), "=r"(r[2]), "=r"(r[3]) : "r"(addr));
}
__device__ __forceinline__ void mma_bf16s(float* c, const uint32_t* a,
                                          uint32_t b0, uint32_t b1) {
    asm volatile(
        "mma.sync.aligned.m16n8k16.row.col.f32.bf16.bf16.f32 "
        "{%0,%1,%2,%3}, {%4,%5,%6,%7}, {%8,%9}, {%0,%1,%2,%3};"
        : "+f"(c[0]), "+f"(c[1]), "+f"(c[2]), "+f"(c[3])
        : "r"(a[0]), "r"(a[1]), "r"(a[2]), "r"(a[3]), "r"(b0), "r"(b1));
}

// ---------------- prep: means, cp, tables ----------------
__global__ void prep_kernel(const float* __restrict__ pos,
                            const float* __restrict__ ef,
                            const float* __restrict__ embed,
                            const float* __restrict__ aW0,
                            const float* __restrict__ ab0,
                            const float* __restrict__ pW0,
                            const float* __restrict__ pb0) {
    const int tid = threadIdx.x; // 256 threads
    __shared__ float sx_[256], sy_[256];

    for (int b = 0; b < BB; b++) {
        float sx = 0.f, sy = 0.f;
        for (int n = tid; n < NN; n += 256) {
            sx += pos[(b * NN + n) * 2 + 0];
            sy += pos[(b * NN + n) * 2 + 1];
        }
        sx_[tid] = sx; sy_[tid] = sy;
        __syncthreads();
        for (int s = 128; s > 0; s >>= 1) {
            if (tid < s) { sx_[tid] += sx_[tid + s]; sy_[tid] += sy_[tid + s]; }
            __syncthreads();
        }
        const float mx = sx_[0] * (1.f / NN);
        const float my = sy_[0] * (1.f / NN);
        for (int n = tid; n < NN; n += 256) {
            g_cp[(b * NN + n) * 2 + 0] = pos[(b * NN + n) * 2 + 0] - mx;
            g_cp[(b * NN + n) * 2 + 1] = pos[(b * NN + n) * 2 + 1] - my;
        }
        __syncthreads();
    }
    {
        const int s = tid >> 6, k = tid & 63;
        float ta = 0.f, tpi = 0.f, tpj = 0.f;
#pragma unroll
        for (int e = 0; e < EE; e++) {
            const float em = embed[s * EE + e];
            ta  += em * aW0[(5 + e) * HH + k];
            tpi += em * pW0[(5 + e) * HH + k];
            tpj += em * pW0[(21 + e) * HH + k];
        }
        g_Tatom[tid] = ta; g_Tpi[tid] = tpi; g_Tpj[tid] = tpj;
    }
    {
        const int b = tid >> 6, k = tid & 63;
        const float Ex = ef[b * 2], Ey = ef[b * 2 + 1];
        const float en = sqrtf(Ex * Ex + Ey * Ey);
        g_ACbase[tid] = Ex * aW0[2 * HH + k] + Ey * aW0[3 * HH + k]
                      + en * aW0[4 * HH + k] + ab0[k];
        g_Pbase[tid]  = en * pW0[4 * HH + k] + pb0[k];
    }
}

// ---------------- atom channel (tiny; known-good f32x2 version) ----------------
__global__ __launch_bounds__(256, 2)
void atom_kernel(const int* __restrict__ species,
                 const float* __restrict__ aW0,
                 const float* __restrict__ aW1,
                 const float* __restrict__ ab1,
                 const float* __restrict__ aW2,
                 const float* __restrict__ ab2) {
    __shared__ __align__(16) float sW1[HH * HH];
    __shared__ float sTA[SS * 65];
    __shared__ float2 sGeo[HH];
    __shared__ __align__(16) float sB1[HH];
    __shared__ float sW2[HH];
    __shared__ float sRed[256];

    const int tid = threadIdx.x;
    const int b = blockIdx.y;
    const int n = blockIdx.x * 256 + tid;

    for (int idx = tid; idx < HH * HH; idx += 256) sW1[idx] = aW1[idx];
    for (int idx = tid; idx < SS * HH; idx += 256) {
        const int s = idx >> 6, k = idx & 63;
        sTA[s * 65 + k] = g_ACbase[b * HH + k] + g_Tatom[s * HH + k];
    }
    if (tid < HH) {
        sGeo[tid] = make_float2(aW0[tid], aW0[HH + tid]);
        sB1[tid] = ab1[tid];
        sW2[tid] = aW2[tid];
    }
    __syncthreads();

    const float cx = g_cp[(b * NN + n) * 2 + 0];
    const float cy = g_cp[(b * NN + n) * 2 + 1];
    const int sp = species[b * NN + n];
    const float* ta = &sTA[sp * 65];

    float h0[HH];
#pragma unroll
    for (int k = 0; k < HH; k++) {
        const float2 g = sGeo[k];
        const float z = fmaf(cx, g.x, fmaf(cy, g.y, ta[k]));
        h0[k] = silu_f(z);
    }

    float e = ab2[0];
#pragma unroll
    for (int kc = 0; kc < HH; kc += 32) {
        u64 acc[16];
        const u64* b1p = (const u64*)&sB1[kc];
#pragma unroll
        for (int m = 0; m < 16; m++) acc[m] = b1p[m];
#pragma unroll
        for (int j = 0; j < HH; j++) {
            const u64 hj = pk2(h0[j], h0[j]);
            const ulonglong2* w = (const ulonglong2*)&sW1[j * HH + kc];
#pragma unroll
            for (int m = 0; m < 8; m++) {
                const ulonglong2 ww = w[m];
                acc[2 * m + 0] = fma2(hj, ww.x, acc[2 * m + 0]);
                acc[2 * m + 1] = fma2(hj, ww.y, acc[2 * m + 1]);
            }
        }
#pragma unroll
        for (int m = 0; m < 16; m++) {
            float z0, z1;
            upk2(acc[m], z0, z1);
            e = fmaf(silu_f(z0), sW2[kc + 2 * m + 0], e);
            e = fmaf(silu_f(z1), sW2[kc + 2 * m + 1], e);
        }
    }

    sRed[tid] = e;
    __syncthreads();
    for (int s = 128; s > 0; s >>= 1) {
        if (tid < s) sRed[tid] += sRed[tid + s];
        __syncthreads();
    }
    if (tid == 0) g_atomPart[b * 4 + blockIdx.x] = sRed[0];
}

// ---------------- pair channel: persistent warp-task HMMA, direct A fragments ----------------
__global__ __launch_bounds__(128, 4)
void pair_mma_kernel(const int* __restrict__ species,
                     const float* __restrict__ ef,
                     const float* __restrict__ pW0,
                     const float* __restrict__ pW1,
                     const float* __restrict__ pb1,
                     const float* __restrict__ pW2,
                     const float* __restrict__ pb2) {
    // static shared: ~37KB -> 4 CTAs/SM
    __shared__ __align__(16) char sBhi[HH * STRIDE_B];
    __shared__ __align__(16) char sBlo[HH * STRIDE_B];
    __shared__ float sTcomb[BB * 16 * TC_STRIDE];
    __shared__ __align__(16) float4 sGeo[HH];
    __shared__ __align__(8) float sB1[HH];
    __shared__ __align__(8) float sW2[HH];
    __shared__ float2 sEF[BB];

    const int tid  = threadIdx.x;
    const int wid  = tid >> 5;
    const int lane = tid & 31;

    // ---- init: B = W1^T (rows n, cols k=j), bf16 hi + residual lo
    for (int idx = tid; idx < HH * HH; idx += 128) {
        const int n = idx >> 6, j = idx & 63;
        const float w = pW1[j * HH + n];
        const __nv_bfloat16 wh = __float2bfloat16_rn(w);
        const float wl = w - __bfloat162float(wh);
        *(__nv_bfloat16*)(sBhi + n * STRIDE_B + j * 2) = wh;
        *(__nv_bfloat16*)(sBlo + n * STRIDE_B + j * 2) = __float2bfloat16_rn(wl);
    }
    for (int idx = tid; idx < BB * 16 * HH; idx += 128) {
        const int bc = idx >> 6, k = idx & 63;
        const int b = bc >> 4, c = bc & 15;
        sTcomb[bc * TC_STRIDE + k] = g_Pbase[b * HH + k]
                                   + g_Tpi[(c >> 2) * HH + k]
                                   + g_Tpj[(c & 3) * HH + k];
    }
    if (tid < HH) {
        sGeo[tid] = make_float4(pW0[0 * HH + tid], pW0[1 * HH + tid],
                                pW0[2 * HH + tid], pW0[3 * HH + tid]);
        sB1[tid] = pb1[tid];
        sW2[tid] = pW2[tid];
    }
    if (tid < BB) sEF[tid] = make_float2(ef[tid * 2], ef[tid * 2 + 1]);
    __syncthreads();

    const uint32_t bhi_u = smem_u32(sBhi);
    const uint32_t blo_u = smem_u32(sBlo);
    const uint32_t lrow = lane & 15, lhalf = (lane >> 4) * 16;
    const int kc4 = (lane & 3) * 2;        // fragment k offset within 16-k step
    const float pb2v = pb2[0];

    float bacc[BB];
#pragma unroll
    for (int b = 0; b < BB; b++) bacc[b] = 0.f;

    const int nwarps = gridDim.x * 4;
    const int gw = blockIdx.x * 4 + wid;

    for (int task = gw; task < NTASKS; task += nwarps) {
        // decode: b, tri -> (ti, tj), il
        const int b = task / (NTRI * 32);
        const int tt = task - b * (NTRI * 32);
        const int tri = tt >> 5, il = tt & 31;
        int rem = tri, ti = 0;
        while (rem >= NT - ti) { rem -= (NT - ti); ti++; }
        const int tj = ti + rem;
        if (ti == tj && il == 31) continue;   // fully-masked row

        const int gi = ti * NT + il;
        const float2 ci = *(const float2*)&g_cp[(b * NN + gi) * 2];
        const int si = species[b * NN + gi];
        const float2 EF = sEF[b];

        // geometry for this thread's 4 fragment rows (pairs)
        float rx[4], ry[4], dd[4], edu[4];
        int tcoff[4], gjr[4];
#pragma unroll
        for (int m = 0; m < 4; m++) {
            const int r = (lane >> 2) + 8 * m;
            const int gj = tj * NT + r;
            gjr[m] = gj;
            const float2 cj = *(const float2*)&g_cp[(b * NN + gj) * 2];
            const int sj = species[b * NN + gj];
            const float x = ci.x - cj.x, y = ci.y - cj.y;
            const float d = sqrtf(x * x + y * y);
            const float dm = fmaxf(d, 1e-12f);
            rx[m] = x; ry[m] = y; dd[m] = d;
            edu[m] = __fdividef(fmaf(EF.x, x, EF.y * y), dm);
            tcoff[m] = (b * 16 + si * 4 + sj) * TC_STRIDE;
        }

        float acc[2][8][4];
#pragma unroll
        for (int mt = 0; mt < 2; mt++)
#pragma unroll
            for (int nt = 0; nt < 8; nt++)
#pragma unroll
                for (int c = 0; c < 4; c++) acc[mt][nt][c] = 0.f;

#pragma unroll
        for (int ks = 0; ks < 4; ks++) {
            const int kb = ks * 16 + kc4;
            const float4 gA = sGeo[kb],     gB = sGeo[kb + 1];
            const float4 gC = sGeo[kb + 8], gD = sGeo[kb + 9];

            // build A fragments directly (hi + residual lo)
            uint32_t ahi[2][4], alo[2][4];
#pragma unroll
            for (int m = 0; m < 4; m++) {
                const float* tc = &sTcomb[tcoff[m]];
                const float2 t01 = *(const float2*)&tc[kb];
                const float2 t89 = *(const float2*)&tc[kb + 8];
                float z0 = t01.x, z1 = t01.y, z8 = t89.x, z9 = t89.y;
                z0 = fmaf(rx[m], gA.x, z0); z0 = fmaf(ry[m], gA.y, z0);
                z0 = fmaf(dd[m], gA.z, z0); z0 = fmaf(edu[m], gA.w, z0);
                z1 = fmaf(rx[m], gB.x, z1); z1 = fmaf(ry[m], gB.y, z1);
                z1 = fmaf(dd[m], gB.z, z1); z1 = fmaf(edu[m], gB.w, z1);
                z8 = fmaf(rx[m], gC.x, z8); z8 = fmaf(ry[m], gC.y, z8);
                z8 = fmaf(dd[m], gC.z, z8); z8 = fmaf(edu[m], gC.w, z8);
                z9 = fmaf(rx[m], gD.x, z9); z9 = fmaf(ry[m], gD.y, z9);
                z9 = fmaf(dd[m], gD.z, z9); z9 = fmaf(edu[m], gD.w, z9);
                const float h0 = silu_f(z0), h1 = silu_f(z1);
                const float h8 = silu_f(z8), h9 = silu_f(z9);
                const uint32_t w01 = packbf2(h1, h0);
                const uint32_t w89 = packbf2(h9, h8);
                const __nv_bfloat162 b01 = *(const __nv_bfloat162*)&w01;
                const __nv_bfloat162 b89 = *(const __nv_bfloat162*)&w89;
                const uint32_t l01 = packbf2(h1 - __bfloat162float(b01.y),
                                             h0 - __bfloat162float(b01.x));
                const uint32_t l89 = packbf2(h9 - __bfloat162float(b89.y),
                                             h8 - __bfloat162float(b89.x));
                const int mt = m >> 1, sl = m & 1;
                ahi[mt][0 + sl] = w01; ahi[mt][2 + sl] = w89;
                alo[mt][0 + sl] = l01; alo[mt][2 + sl] = l89;
            }

            const uint32_t koff = ks * 32 + lhalf;
#pragma unroll
            for (int nq = 0; nq < 4; nq++) {
                uint32_t rb[4], rl[4];
                ldsm4(rb, bhi_u + (nq * 16 + lrow) * STRIDE_B + koff);
                ldsm4(rl, blo_u + (nq * 16 + lrow) * STRIDE_B + koff);
#pragma unroll
                for (int mt = 0; mt < 2; mt++) {
                    mma_bf16s(acc[mt][2 * nq],     ahi[mt], rb[0], rb[2]);
                    mma_bf16s(acc[mt][2 * nq],     ahi[mt], rl[0], rl[2]);
                    mma_bf16s(acc[mt][2 * nq],     alo[mt], rb[0], rb[2]);
                    mma_bf16s(acc[mt][2 * nq + 1], ahi[mt], rb[1], rb[3]);
                    mma_bf16s(acc[mt][2 * nq + 1], ahi[mt], rl[1], rl[3]);
                    mma_bf16s(acc[mt][2 * nq + 1], alo[mt], rb[1], rb[3]);
                }
            }
        }

        // ---- epilogue: bias + silu + dot W2 per fragment row
        float s[4] = {0.f, 0.f, 0.f, 0.f};
#pragma unroll
        for (int nt = 0; nt < 8; nt++) {
            const int n0 = nt * 8 + kc4;
            const float2 b1 = *(const float2*)&sB1[n0];
            const float2 w2 = *(const float2*)&sW2[n0];
#pragma unroll
            for (int mt = 0; mt < 2; mt++) {
                s[mt * 2 + 0] = fmaf(silu_f(acc[mt][nt][0] + b1.x), w2.x, s[mt * 2 + 0]);
                s[mt * 2 + 0] = fmaf(silu_f(acc[mt][nt][1] + b1.y), w2.y, s[mt * 2 + 0]);
                s[mt * 2 + 1] = fmaf(silu_f(acc[mt][nt][2] + b1.x), w2.x, s[mt * 2 + 1]);
                s[mt * 2 + 1] = fmaf(silu_f(acc[mt][nt][3] + b1.y), w2.y, s[mt * 2 + 1]);
            }
        }
        float v = 0.f;
        int cnt = 0;
#pragma unroll
        for (int m = 0; m < 4; m++) {
            const bool mk = gi < gjr[m];
            v += mk ? s[m] : 0.f;
            cnt += (int)mk;
        }
        v += __shfl_xor_sync(0xFFFFFFFFu, v, 1);
        v += __shfl_xor_sync(0xFFFFFFFFu, v, 2);
        v = ((lane & 3) == 0) ? fmaf(pb2v, (float)cnt, v) : 0.f;
        v += __shfl_xor_sync(0xFFFFFFFFu, v, 4);
        v += __shfl_xor_sync(0xFFFFFFFFu, v, 8);
        v += __shfl_xor_sync(0xFFFFFFFFu, v, 16);
        if (lane == 0) bacc[b] += v;
    }

    if (lane == 0) {
#pragma unroll
        for (int b = 0; b < BB; b++) g_pairW[b * MAXW + gw] = bacc[b];
    }
}

// ---------------- deterministic parallel finalize ----------------
__global__ void finalize_kernel(float* __restrict__ out) {
    __shared__ float red[256];
    const int tid = threadIdx.x;
    const int b = tid >> 6, lane = tid & 63;
    float s = 0.f;
    for (int i = lane; i < MAXW; i += 64) s += g_pairW[b * MAXW + i];
    if (lane < 4) s += g_atomPart[b * 4 + lane];
    red[tid] = s;
    __syncthreads();
    for (int st = 32; st > 0; st >>= 1) {
        if (lane < st) red[tid] += red[tid + st];
        __syncthreads();
    }
    if (lane == 0) out[b] = red[tid];
}

// ---------------- launch ----------------
extern "C" void kernel_launch(void* const* d_in, const int* in_sizes, int n_in,
                              void* d_out, int out_size) {
    const float* positions = (const float*)d_in[0];
    const int*   species   = (const int*)d_in[1];
    const float* efield    = (const float*)d_in[2];
    const float* embed     = (const float*)d_in[3];
    const float* aW0 = (const float*)d_in[4];
    const float* ab0 = (const float*)d_in[5];
    const float* aW1 = (const float*)d_in[6];
    const float* ab1 = (const float*)d_in[7];
    const float* aW2 = (const float*)d_in[8];
    const float* ab2 = (const float*)d_in[9];
    const float* pW0 = (const float*)d_in[10];
    const float* pb0 = (const float*)d_in[11];
    const float* pW1 = (const float*)d_in[12];
    const float* pb1 = (const float*)d_in[13];
    const float* pW2 = (const float*)d_in[14];
    const float* pb2 = (const float*)d_in[15];
    float* out = (float*)d_out;

    int sms = 148;
    cudaDeviceGetAttribute(&sms, cudaDevAttrMultiProcessorCount, 0);
    int grid_pair = 4 * sms;
    if (grid_pair > MAX_CTAS) grid_pair = MAX_CTAS;

    prep_kernel<<<1, 256>>>(positions, efield, embed, aW0, ab0, pW0, pb0);
    atom_kernel<<<dim3(4, BB), 256>>>(species, aW0, aW1, ab1, aW2, ab2);
    pair_mma_kernel<<<grid_pair, 128>>>(species, efield, pW0, pW1, pb1, pW2, pb2);
    finalize_kernel<<<1, 256>>>(out);
}

// round 11
// speedup vs baseline: 4.7360x; 1.5708x over previous
#include <cuda_runtime.h>
#include <cuda_bf16.h>
#include <math.h>
#include <stdint.h>

// Problem constants (fixed shapes)
#define BB 4
#define NN 1024
#define EE 16
#define SS 4
#define HH 64          // AH == PH == 64
#define NT 32          // tiles per dimension (N/32)
#define NTRI 528       // triangular 32x32 tiles per batch
#define NTASKS (BB * NTRI * 32)      // 67584 warp-tasks (one i-row x 32 j)

#define MAX_CTAS 640
#define MAXW (MAX_CTAS * 4)          // 2560 warp slots

#define STRIDE_B 144                 // 72 bf16 per row: conflict-free ldmatrix
#define TC_STRIDE 66                 // even stride -> aligned float2/u64

typedef unsigned long long u64;

// ---------------- device scratch (no allocations allowed) ----------------
__device__ float g_cp[BB * NN * 2];
__device__ float g_Tatom[SS * HH];
__device__ float g_Tpi[SS * HH];
__device__ float g_Tpj[SS * HH];
__device__ float g_ACbase[BB * HH];
__device__ float g_Pbase[BB * HH];
__device__ float g_pairW[BB * MAXW];   // zero-init; unlaunched slots stay 0
__device__ float g_atomPart[BB * 4];

// ---------------- small helpers ----------------
__device__ __forceinline__ u64 pk2(float a, float b) {
    u64 r; asm("mov.b64 %0, {%1, %2};" : "=l"(r) : "f"(a), "f"(b)); return r;
}
__device__ __forceinline__ u64 fma2(u64 a, u64 b, u64 c) {
    u64 d; asm("fma.rn.f32x2 %0, %1, %2, %3;" : "=l"(d) : "l"(a), "l"(b), "l"(c)); return d;
}
__device__ __forceinline__ void upk2(u64 v, float& x, float& y) {
    asm("mov.b64 {%0, %1}, %2;" : "=f"(x), "=f"(y) : "l"(v));
}
// exact-ish silu (atom channel)
__device__ __forceinline__ float silu_f(float x) {
    const float t = __expf(-x);
    return __fdividef(x, 1.0f + t);
}
// fast silu via tanh.approx: silu(x) = hx + hx*tanh(hx), hx = x/2
__device__ __forceinline__ float silu_t(float x) {
    const float hx = 0.5f * x;
    float t;
    asm("tanh.approx.f32 %0, %1;" : "=f"(t) : "f"(hx));
    return fmaf(hx, t, hx);
}
__device__ __forceinline__ uint32_t smem_u32(const void* p) {
    uint32_t a;
    asm("{ .reg .u64 tmp; cvta.to.shared.u64 tmp, %1; cvt.u32.u64 %0, tmp; }"
        : "=r"(a) : "l"(p));
    return a;
}
// bf16x2 pack: word = {hi = odd-k value, lo = even-k value}
__device__ __forceinline__ uint32_t packbf2(float odd, float even) {
    uint32_t w;
    asm("cvt.rn.bf16x2.f32 %0, %1, %2;" : "=r"(w) : "f"(odd), "f"(even));
    return w;
}
__device__ __forceinline__ void ldsm4(uint32_t* r, uint32_t addr) {
    asm volatile("ldmatrix.sync.aligned.m8n8.x4.shared.b16 {%0,%1,%2,%3}, [%4];"
                 : "=r"(r[0]), "=r"(r[1]), "=r"(r[2]), "=r"(r[3]) : "r"(addr));
}
__device__ __forceinline__ void mma_bf16s(float* c, const uint32_t* a,
                                          uint32_t b0, uint32_t b1) {
    asm volatile(
        "mma.sync.aligned.m16n8k16.row.col.f32.bf16.bf16.f32 "
        "{%0,%1,%2,%3}, {%4,%5,%6,%7}, {%8,%9}, {%0,%1,%2,%3};"
        : "+f"(c[0]), "+f"(c[1]), "+f"(c[2]), "+f"(c[3])
        : "r"(a[0]), "r"(a[1]), "r"(a[2]), "r"(a[3]), "r"(b0), "r"(b1));
}

// ---------------- prep: means, cp, tables (parallel over batches) ----------------
__global__ void prep_kernel(const float* __restrict__ pos,
                            const float* __restrict__ ef,
                            const float* __restrict__ embed,
                            const float* __restrict__ aW0,
                            const float* __restrict__ ab0,
                            const float* __restrict__ pW0,
                            const float* __restrict__ pb0) {
    const int tid = threadIdx.x; // 256 threads
    const int b = blockIdx.x;    // one block per batch
    __shared__ float sx_[256], sy_[256];

    float sx = 0.f, sy = 0.f;
    for (int n = tid; n < NN; n += 256) {
        sx += pos[(b * NN + n) * 2 + 0];
        sy += pos[(b * NN + n) * 2 + 1];
    }
    sx_[tid] = sx; sy_[tid] = sy;
    __syncthreads();
    for (int s = 128; s > 0; s >>= 1) {
        if (tid < s) { sx_[tid] += sx_[tid + s]; sy_[tid] += sy_[tid + s]; }
        __syncthreads();
    }
    const float mx = sx_[0] * (1.f / NN);
    const float my = sy_[0] * (1.f / NN);
    for (int n = tid; n < NN; n += 256) {
        g_cp[(b * NN + n) * 2 + 0] = pos[(b * NN + n) * 2 + 0] - mx;
        g_cp[(b * NN + n) * 2 + 1] = pos[(b * NN + n) * 2 + 1] - my;
    }

    if (b == 0) {   // species tables: 256 entries, one per thread
        const int s = tid >> 6, k = tid & 63;
        float ta = 0.f, tpi = 0.f, tpj = 0.f;
#pragma unroll
        for (int e = 0; e < EE; e++) {
            const float em = embed[s * EE + e];
            ta  += em * aW0[(5 + e) * HH + k];
            tpi += em * pW0[(5 + e) * HH + k];
            tpj += em * pW0[(21 + e) * HH + k];
        }
        g_Tatom[tid] = ta; g_Tpi[tid] = tpi; g_Tpj[tid] = tpj;
    }
    if (tid < HH) {
        const int k = tid;
        const float Ex = ef[b * 2], Ey = ef[b * 2 + 1];
        const float en = sqrtf(Ex * Ex + Ey * Ey);
        g_ACbase[b * HH + k] = Ex * aW0[2 * HH + k] + Ey * aW0[3 * HH + k]
                             + en * aW0[4 * HH + k] + ab0[k];
        g_Pbase[b * HH + k]  = en * pW0[4 * HH + k] + pb0[k];
    }
}

// ---------------- atom channel (tiny; known-good f32x2 version) ----------------
__global__ __launch_bounds__(256, 2)
void atom_kernel(const int* __restrict__ species,
                 const float* __restrict__ aW0,
                 const float* __restrict__ aW1,
                 const float* __restrict__ ab1,
                 const float* __restrict__ aW2,
                 const float* __restrict__ ab2) {
    __shared__ __align__(16) float sW1[HH * HH];
    __shared__ float sTA[SS * 65];
    __shared__ float2 sGeo[HH];
    __shared__ __align__(16) float sB1[HH];
    __shared__ float sW2[HH];
    __shared__ float sRed[256];

    const int tid = threadIdx.x;
    const int b = blockIdx.y;
    const int n = blockIdx.x * 256 + tid;

    for (int idx = tid; idx < HH * HH; idx += 256) sW1[idx] = aW1[idx];
    for (int idx = tid; idx < SS * HH; idx += 256) {
        const int s = idx >> 6, k = idx & 63;
        sTA[s * 65 + k] = g_ACbase[b * HH + k] + g_Tatom[s * HH + k];
    }
    if (tid < HH) {
        sGeo[tid] = make_float2(aW0[tid], aW0[HH + tid]);
        sB1[tid] = ab1[tid];
        sW2[tid] = aW2[tid];
    }
    __syncthreads();

    const float cx = g_cp[(b * NN + n) * 2 + 0];
    const float cy = g_cp[(b * NN + n) * 2 + 1];
    const int sp = species[b * NN + n];
    const float* ta = &sTA[sp * 65];

    float h0[HH];
#pragma unroll
    for (int k = 0; k < HH; k++) {
        const float2 g = sGeo[k];
        const float z = fmaf(cx, g.x, fmaf(cy, g.y, ta[k]));
        h0[k] = silu_f(z);
    }

    float e = ab2[0];
#pragma unroll
    for (int kc = 0; kc < HH; kc += 32) {
        u64 acc[16];
        const u64* b1p = (const u64*)&sB1[kc];
#pragma unroll
        for (int m = 0; m < 16; m++) acc[m] = b1p[m];
#pragma unroll
        for (int j = 0; j < HH; j++) {
            const u64 hj = pk2(h0[j], h0[j]);
            const ulonglong2* w = (const ulonglong2*)&sW1[j * HH + kc];
#pragma unroll
            for (int m = 0; m < 8; m++) {
                const ulonglong2 ww = w[m];
                acc[2 * m + 0] = fma2(hj, ww.x, acc[2 * m + 0]);
                acc[2 * m + 1] = fma2(hj, ww.y, acc[2 * m + 1]);
            }
        }
#pragma unroll
        for (int m = 0; m < 16; m++) {
            float z0, z1;
            upk2(acc[m], z0, z1);
            e = fmaf(silu_f(z0), sW2[kc + 2 * m + 0], e);
            e = fmaf(silu_f(z1), sW2[kc + 2 * m + 1], e);
        }
    }

    sRed[tid] = e;
    __syncthreads();
    for (int s = 128; s > 0; s >>= 1) {
        if (tid < s) sRed[tid] += sRed[tid + s];
        __syncthreads();
    }
    if (tid == 0) g_atomPart[b * 4 + blockIdx.x] = sRed[0];
}

// ---------------- pair channel: persistent warp-task HMMA ----------------
// 2-term compensated MMA: Ahi*(Bhi + Blo). A-residual (per-pair rounding noise,
// random sign) is dropped; B-residual (systematic weight rounding) is kept.
__global__ __launch_bounds__(128, 4)
void pair_mma_kernel(const int* __restrict__ species,
                     const float* __restrict__ ef,
                     const float* __restrict__ pW0,
                     const float* __restrict__ pW1,
                     const float* __restrict__ pb1,
                     const float* __restrict__ pW2,
                     const float* __restrict__ pb2) {
    __shared__ __align__(16) char sBhi[HH * STRIDE_B];
    __shared__ __align__(16) char sBlo[HH * STRIDE_B];
    __shared__ __align__(16) float sTcomb[BB * 16 * TC_STRIDE];
    __shared__ __align__(16) u64 sGx[32], sGy[32], sGz[32], sGw[32];
    __shared__ __align__(8) float sB1[HH];
    __shared__ __align__(8) float sW2[HH];
    __shared__ float2 sEF[BB];

    const int tid  = threadIdx.x;
    const int wid  = tid >> 5;
    const int lane = tid & 31;

    // ---- init: B = W1^T (rows n, cols k=j), bf16 hi + residual lo
    for (int idx = tid; idx < HH * HH; idx += 128) {
        const int n = idx >> 6, j = idx & 63;
        const float w = pW1[j * HH + n];
        const __nv_bfloat16 wh = __float2bfloat16_rn(w);
        const float wl = w - __bfloat162float(wh);
        *(__nv_bfloat16*)(sBhi + n * STRIDE_B + j * 2) = wh;
        *(__nv_bfloat16*)(sBlo + n * STRIDE_B + j * 2) = __float2bfloat16_rn(wl);
    }
    for (int idx = tid; idx < BB * 16 * HH; idx += 128) {
        const int bc = idx >> 6, k = idx & 63;
        const int b = bc >> 4, c = bc & 15;
        sTcomb[bc * TC_STRIDE + k] = g_Pbase[b * HH + k]
                                   + g_Tpi[(c >> 2) * HH + k]
                                   + g_Tpj[(c & 3) * HH + k];
    }
    if (tid < 32) {   // pair-packed geometry tables
        const int k = tid * 2;
        sGx[tid] = pk2(pW0[0 * HH + k], pW0[0 * HH + k + 1]);
        sGy[tid] = pk2(pW0[1 * HH + k], pW0[1 * HH + k + 1]);
        sGz[tid] = pk2(pW0[2 * HH + k], pW0[2 * HH + k + 1]);
        sGw[tid] = pk2(pW0[3 * HH + k], pW0[3 * HH + k + 1]);
    }
    if (tid < HH) {
        sB1[tid] = pb1[tid];
        sW2[tid] = pW2[tid];
    }
    if (tid < BB) sEF[tid] = make_float2(ef[tid * 2], ef[tid * 2 + 1]);
    __syncthreads();

    const uint32_t bhi_u = smem_u32(sBhi);
    const uint32_t blo_u = smem_u32(sBlo);
    const uint32_t lrow = lane & 15, lhalf = (lane >> 4) * 16;
    const int kc4 = (lane & 3) * 2;        // fragment k offset within 16-k step
    const float pb2v = pb2[0];

    float bacc[BB];
#pragma unroll
    for (int b = 0; b < BB; b++) bacc[b] = 0.f;

    const int nwarps = gridDim.x * 4;
    const int gw = blockIdx.x * 4 + wid;

    for (int task = gw; task < NTASKS; task += nwarps) {
        // decode: b, tri -> (ti, tj), il
        const int b = task / (NTRI * 32);
        const int tt = task - b * (NTRI * 32);
        const int tri = tt >> 5, il = tt & 31;
        int rem = tri, ti = 0;
        while (rem >= NT - ti) { rem -= (NT - ti); ti++; }
        const int tj = ti + rem;
        if (ti == tj && il == 31) continue;   // fully-masked row

        const int gi = ti * NT + il;
        const float2 ci = *(const float2*)&g_cp[(b * NN + gi) * 2];
        const int si = species[b * NN + gi];
        const float2 EF = sEF[b];

        // geometry for this thread's 4 fragment rows (pairs)
        float rx[4], ry[4], dd[4], edu[4];
        int tcoff[4];
#pragma unroll
        for (int m = 0; m < 4; m++) {
            const int gj = tj * NT + (lane >> 2) + 8 * m;
            const float2 cj = *(const float2*)&g_cp[(b * NN + gj) * 2];
            const int sj = species[b * NN + gj];
            const float x = ci.x - cj.x, y = ci.y - cj.y;
            const float d = sqrtf(x * x + y * y);
            const float dm = fmaxf(d, 1e-12f);
            rx[m] = x; ry[m] = y; dd[m] = d;
            edu[m] = __fdividef(fmaf(EF.x, x, EF.y * y), dm);
            tcoff[m] = (b * 16 + si * 4 + sj) * TC_STRIDE;
        }

        // acc init = bias (folded layer-1 bias)
        float acc[2][8][4];
#pragma unroll
        for (int nt = 0; nt < 8; nt++) {
            const float2 b1 = *(const float2*)&sB1[nt * 8 + kc4];
#pragma unroll
            for (int mt = 0; mt < 2; mt++) {
                acc[mt][nt][0] = b1.x; acc[mt][nt][1] = b1.y;
                acc[mt][nt][2] = b1.x; acc[mt][nt][3] = b1.y;
            }
        }

#pragma unroll
        for (int ks = 0; ks < 4; ks++) {
            const int p0 = ks * 8 + (lane & 3);
            const u64 gx0 = sGx[p0],     gy0 = sGy[p0];
            const u64 gz0 = sGz[p0],     gw0 = sGw[p0];
            const u64 gx1 = sGx[p0 + 4], gy1 = sGy[p0 + 4];
            const u64 gz1 = sGz[p0 + 4], gw1 = sGw[p0 + 4];
            const int kb = ks * 16 + kc4;

            uint32_t ahi[2][4];
#pragma unroll
            for (int m = 0; m < 4; m++) {
                const u64 rx2 = pk2(rx[m], rx[m]);
                const u64 ry2 = pk2(ry[m], ry[m]);
                const u64 dd2 = pk2(dd[m], dd[m]);
                const u64 ee2 = pk2(edu[m], edu[m]);
                const float* tc = &sTcomb[tcoff[m]];
                u64 z01 = *(const u64*)(tc + kb);
                z01 = fma2(rx2, gx0, z01); z01 = fma2(ry2, gy0, z01);
                z01 = fma2(dd2, gz0, z01); z01 = fma2(ee2, gw0, z01);
                u64 z89 = *(const u64*)(tc + kb + 8);
                z89 = fma2(rx2, gx1, z89); z89 = fma2(ry2, gy1, z89);
                z89 = fma2(dd2, gz1, z89); z89 = fma2(ee2, gw1, z89);
                float z0, z1, z8, z9;
                upk2(z01, z0, z1); upk2(z89, z8, z9);
                const float h0 = silu_t(z0), h1 = silu_t(z1);
                const float h8 = silu_t(z8), h9 = silu_t(z9);
                const int mt = m >> 1, sl = m & 1;
                ahi[mt][0 + sl] = packbf2(h1, h0);
                ahi[mt][2 + sl] = packbf2(h9, h8);
            }

            const uint32_t koff = ks * 32 + lhalf;
#pragma unroll
            for (int nq = 0; nq < 4; nq++) {
                uint32_t rb[4], rl[4];
                ldsm4(rb, bhi_u + (nq * 16 + lrow) * STRIDE_B + koff);
                ldsm4(rl, blo_u + (nq * 16 + lrow) * STRIDE_B + koff);
#pragma unroll
                for (int mt = 0; mt < 2; mt++) {
                    mma_bf16s(acc[mt][2 * nq],     ahi[mt], rb[0], rb[2]);
                    mma_bf16s(acc[mt][2 * nq],     ahi[mt], rl[0], rl[2]);
                    mma_bf16s(acc[mt][2 * nq + 1], ahi[mt], rb[1], rb[3]);
                    mma_bf16s(acc[mt][2 * nq + 1], ahi[mt], rl[1], rl[3]);
                }
            }
        }

        // ---- epilogue: silu + dot W2 per fragment row (bias already in acc)
        float s[4] = {0.f, 0.f, 0.f, 0.f};
#pragma unroll
        for (int nt = 0; nt < 8; nt++) {
            const float2 w2 = *(const float2*)&sW2[nt * 8 + kc4];
#pragma unroll
            for (int mt = 0; mt < 2; mt++) {
                s[mt * 2 + 0] = fmaf(silu_t(acc[mt][nt][0]), w2.x, s[mt * 2 + 0]);
                s[mt * 2 + 0] = fmaf(silu_t(acc[mt][nt][1]), w2.y, s[mt * 2 + 0]);
                s[mt * 2 + 1] = fmaf(silu_t(acc[mt][nt][2]), w2.x, s[mt * 2 + 1]);
                s[mt * 2 + 1] = fmaf(silu_t(acc[mt][nt][3]), w2.y, s[mt * 2 + 1]);
            }
        }
        float v = 0.f;
        int cnt = 0;
#pragma unroll
        for (int m = 0; m < 4; m++) {
            const bool mk = gi < (tj * NT + (lane >> 2) + 8 * m);
            v += mk ? s[m] : 0.f;
            cnt += (int)mk;
        }
        v += __shfl_xor_sync(0xFFFFFFFFu, v, 1);
        v += __shfl_xor_sync(0xFFFFFFFFu, v, 2);
        v = ((lane & 3) == 0) ? fmaf(pb2v, (float)cnt, v) : 0.f;
        v += __shfl_xor_sync(0xFFFFFFFFu, v, 4);
        v += __shfl_xor_sync(0xFFFFFFFFu, v, 8);
        v += __shfl_xor_sync(0xFFFFFFFFu, v, 16);
        if (lane == 0) bacc[b] += v;
    }

    if (lane == 0) {
#pragma unroll
        for (int b = 0; b < BB; b++) g_pairW[b * MAXW + gw] = bacc[b];
    }
}

// ---------------- deterministic parallel finalize ----------------
__global__ void finalize_kernel(float* __restrict__ out) {
    __shared__ float red[1024];
    const int tid = threadIdx.x;
    const int b = tid >> 8, lane = tid & 255;
    float s = 0.f;
    for (int i = lane; i < MAXW; i += 256) s += g_pairW[b * MAXW + i];
    if (lane < 4) s += g_atomPart[b * 4 + lane];
    red[tid] = s;
    __syncthreads();
    for (int st = 128; st > 0; st >>= 1) {
        if (lane < st) red[tid] += red[tid + st];
        __syncthreads();
    }
    if (lane == 0) out[b] = red[tid];
}

// ---------------- launch ----------------
extern "C" void kernel_launch(void* const* d_in, const int* in_sizes, int n_in,
                              void* d_out, int out_size) {
    const float* positions = (const float*)d_in[0];
    const int*   species   = (const int*)d_in[1];
    const float* efield    = (const float*)d_in[2];
    const float* embed     = (const float*)d_in[3];
    const float* aW0 = (const float*)d_in[4];
    const float* ab0 = (const float*)d_in[5];
    const float* aW1 = (const float*)d_in[6];
    const float* ab1 = (const float*)d_in[7];
    const float* aW2 = (const float*)d_in[8];
    const float* ab2 = (const float*)d_in[9];
    const float* pW0 = (const float*)d_in[10];
    const float* pb0 = (const float*)d_in[11];
    const float* pW1 = (const float*)d_in[12];
    const float* pb1 = (const float*)d_in[13];
    const float* pW2 = (const float*)d_in[14];
    const float* pb2 = (const float*)d_in[15];
    float* out = (float*)d_out;

    int sms = 148;
    cudaDeviceGetAttribute(&sms, cudaDevAttrMultiProcessorCount, 0);
    int grid_pair = 4 * sms;
    if (grid_pair > MAX_CTAS) grid_pair = MAX_CTAS;

    prep_kernel<<<BB, 256>>>(positions, efield, embed, aW0, ab0, pW0, pb0);
    atom_kernel<<<dim3(4, BB), 256>>>(species, aW0, aW1, ab1, aW2, ab2);
    pair_mma_kernel<<<grid_pair, 128>>>(species, efield, pW0, pW1, pb1, pW2, pb2);
    finalize_kernel<<<1, 1024>>>(out);
}